// round 6
// baseline (speedup 1.0000x reference)
#include <cuda_runtime.h>
#include <math.h>

#define B 4
#define HW 48
#define PIX 2304        // 48*48
#define D 64
#define JH 46
#define C 2116          // 46*46
#define CP 48           // padded inner dim
#define NSPLIT 4
#define KSEG (PIX/NSPLIT)   // 576

// ---------------- scratch (device globals; per-batch reuse, ~115MB) ----------------
__device__ float d_bg[B*PIX*D];
__device__ float d_ng[B*PIX];
__device__ float d_nbg[B*PIX];
__device__ float d_wwd[B*PIX];
__device__ float d_k1d[B*C];
__device__ float d_G[PIX*PIX];            // gram, one batch (21.2MB)
__device__ float d_Hh[HW*HW*JH*HW];       // y-diag sum of G (20.3MB)
__device__ float d_CA[PIX*JH*CP];         // attention, PADDED rows [jy][48] (20.3MB)
__device__ float d_Pm[HW*HW*HW*CP];       // y-diag sum of CA, PADDED v->48 (21.2MB)
__device__ float d_CB[PIX*PIX];           // diag box sum of CA (21.2MB)
__device__ float d_aclp[NSPLIT][PIX*D];

// ---------------- f32x2 packed FMA ----------------
__device__ __forceinline__ void ffma2(unsigned long long& d,
                                      unsigned long long a,
                                      unsigned long long b) {
    asm("fma.rn.f32x2 %0, %1, %2, %3;" : "=l"(d) : "l"(a), "l"(b), "l"(d));
}
__device__ __forceinline__ float pairsum(unsigned long long p) {
    float lo = __uint_as_float((unsigned)(p & 0xffffffffull));
    float hi = __uint_as_float((unsigned)(p >> 32));
    return lo + hi;
}

// ---------------- block reduction (256 threads, 8 warps) ----------------
__device__ __forceinline__ float blkSum(float v, volatile float* sh) {
    for (int o = 16; o; o >>= 1) v += __shfl_down_sync(0xffffffffu, v, o);
    int w = threadIdx.x >> 5;
    if ((threadIdx.x & 31) == 0) sh[w] = v;
    __syncthreads();
    if (threadIdx.x == 0) {
        float s = 0.f;
        for (int i = 0; i < 8; i++) s += sh[i];
        sh[0] = s;
    }
    __syncthreads();
    float r = sh[0];
    __syncthreads();
    return r;
}

// ---------------- K1: bg + pixel norms (all batches) ----------------
__global__ void prep_kernel(const float* __restrict__ g_in,
                            const float* __restrict__ mask) {
    int pix = blockIdx.x * 4 + (threadIdx.x >> 6);
    int ch  = threadIdx.x & 63;
    float g = g_in[pix * D + ch];
    float m = mask[pix];
    float bgv = g * m;
    d_bg[pix * D + ch] = bgv;
    float ng = g * g, nb = bgv * bgv;
    for (int o = 16; o; o >>= 1) {
        ng += __shfl_down_sync(0xffffffffu, ng, o);
        nb += __shfl_down_sync(0xffffffffu, nb, o);
    }
    __shared__ float sng[8], snb[8];
    int w = threadIdx.x >> 5;
    if ((threadIdx.x & 31) == 0) { sng[w] = ng; snb[w] = nb; }
    __syncthreads();
    if (ch == 0) {
        d_ng[pix]  = sng[w] + sng[w + 1];
        d_nbg[pix] = snb[w] + snb[w + 1];
    }
}

// ---------------- K2: box sums (all batches) ----------------
__global__ void box_kernel() {
    int idx = blockIdx.x * blockDim.x + threadIdx.x;
    if (idx >= B * PIX) return;
    int b = idx / PIX, p = idx % PIX;
    int y = p / HW, x = p % HW;
    float s = 0.f;
    for (int dy = 0; dy < 3; dy++)
        for (int dx = 0; dx < 3; dx++) {
            int yy = y + dy - 1, xx = x + dx - 1;
            if ((unsigned)yy < (unsigned)HW && (unsigned)xx < (unsigned)HW)
                s += d_ng[b * PIX + yy * HW + xx];
        }
    d_wwd[idx] = s;
    if (y < JH && x < JH) {
        float s2 = 0.f;
        for (int dy = 0; dy < 3; dy++)
            for (int dx = 0; dx < 3; dx++)
                s2 += d_nbg[b * PIX + (y + dy) * HW + (x + dx)];
        d_k1d[b * C + y * JH + x] = s2;
    }
}

// ---------------- K3: G = g_in @ bg^T (one batch), f32x2 packed ----------------
__global__ void gemmG_kernel(const float* __restrict__ g_in, int b) {
    __shared__ __align__(16) float As[64 * 66];
    __shared__ __align__(16) float Bs[64 * 66];
    int pt = blockIdx.y * 64, qt = blockIdx.x * 64;
    const float* Ap = g_in + (size_t)b * PIX * D;
    const float* Bp = d_bg + (size_t)b * PIX * D;
    int tid = threadIdx.x;
    for (int i = tid; i < 4096; i += 256) {
        int r = i >> 6, c = i & 63;
        As[r * 66 + c] = Ap[(pt + r) * D + c];
        Bs[r * 66 + c] = Bp[(qt + r) * D + c];
    }
    __syncthreads();
    int ty = tid >> 4, tx = tid & 15;
    unsigned long long acc[4][4] = {};
#pragma unroll
    for (int kp = 0; kp < 32; kp++) {
        int k = kp * 2;
        unsigned long long a2[4], b2[4];
#pragma unroll
        for (int i = 0; i < 4; i++) {
            a2[i] = *(const unsigned long long*)&As[(ty + 16 * i) * 66 + k];
            b2[i] = *(const unsigned long long*)&Bs[(tx + 16 * i) * 66 + k];
        }
#pragma unroll
        for (int i = 0; i < 4; i++)
#pragma unroll
            for (int j = 0; j < 4; j++) ffma2(acc[i][j], a2[i], b2[j]);
    }
#pragma unroll
    for (int i = 0; i < 4; i++)
#pragma unroll
        for (int j = 0; j < 4; j++)
            d_G[(size_t)(pt + ty + 16 * i) * PIX + qt + tx + 16 * j] = pairsum(acc[i][j]);
}

// ---------------- K4: Hh[y][px][jy][qx] = sum_dy G[(y+dy-1,px)][(jy+dy)*48+qx], float4 ----------------
__global__ void hbuild_kernel() {
    const int n4 = HW * HW * JH * (HW / 4);   // 1,271,808
    int idx = blockIdx.x * blockDim.x + threadIdx.x;
    if (idx >= n4) return;
    int q4 = idx % 12; int t = idx / 12;
    int jy = t % JH;   t /= JH;
    int px = t % HW;   int y = t / HW;
    const float4* G4 = (const float4*)d_G;
    float4 s = make_float4(0.f, 0.f, 0.f, 0.f);
#pragma unroll
    for (int dy = 0; dy < 3; dy++) {
        int yy = y + dy - 1;
        if ((unsigned)yy < (unsigned)HW) {
            float4 g = G4[(size_t)(yy * HW + px) * (PIX / 4) + (jy + dy) * 12 + q4];
            s.x += g.x; s.y += g.y; s.z += g.z; s.w += g.w;
        }
    }
    ((float4*)d_Hh)[idx] = s;
}

// ---------------- K5: fused CS row + stats + tanh + softmax -> CA (padded rows) ----------------
__global__ void row_kernel(int b) {
    __shared__ float rowbuf[C];
    __shared__ float red[8];
    int p = blockIdx.x;
    int y = p / HW, x = p % HW;
    int tid = threadIdx.x;
    float wv = d_wwd[b * PIX + p];

    // pass 1: DS1 = k1d + wwd - 2*CS, accumulate sum
    float s = 0.f;
    for (int j = tid; j < C; j += 256) {
        int jy = j / JH, jx = j - jy * JH;
        float cs = 0.f;
#pragma unroll
        for (int dx = 0; dx < 3; dx++) {
            int xx = x + dx - 1;
            if ((unsigned)xx < (unsigned)HW)
                cs += d_Hh[((y * HW + xx) * JH + jy) * HW + (jx + dx)];
        }
        float ds = d_k1d[b * C + j] + wv - 2.f * cs;
        rowbuf[j] = ds;
        s += ds;
    }
    float mu = blkSum(s, red) * (1.f / (float)C);

    // pass 2: variance (two-pass for accuracy)
    float s2 = 0.f;
    for (int j = tid; j < C; j += 256) { float d = rowbuf[j] - mu; s2 += d * d; }
    float var = blkSum(s2, red) * (1.f / (float)C);
    float inv_sd = rsqrtf(var);

    // pass 3: e = exp(-50*tanh(t) - 50), overflow-free form exp(-100*sigmoid(2t));
    // max logit >= 0 always (mean-centered), so fixed shift of 50 is safe.
    float se = 0.f;
    for (int j = tid; j < C; j += 256) {
        float t = (rowbuf[j] - mu) * inv_sd;
        float e = __expf(-100.f / (1.f + __expf(-2.f * t)));
        rowbuf[j] = e;
        se += e;
    }
    float invZ = 1.f / blkSum(se, red);

    // pass 4: write CA (padded [jy][48] rows)
    for (int j = tid; j < C; j += 256) {
        int jy = j / JH, jx = j - jy * JH;
        d_CA[((size_t)p * JH + jy) * CP + jx] = rowbuf[j] * invZ;
    }
}

// ---------------- K6: Pm[y][x][u][v<48] = sum_dy CA[(y+1-dy,x)][(u-dy)][v], float4 ----------------
__global__ void pm_kernel() {
    const int n4 = HW * HW * HW * (CP / 4);   // 1,327,104
    int idx = blockIdx.x * blockDim.x + threadIdx.x;
    if (idx >= n4) return;
    int q4 = idx % 12; int t = idx / 12;
    int u = t % HW;    t /= HW;
    int x = t % HW;    int y = t / HW;
    const float4* CA4 = (const float4*)d_CA;
    float4 s = make_float4(0.f, 0.f, 0.f, 0.f);
#pragma unroll
    for (int dy = 0; dy < 3; dy++) {
        int yy = y + 1 - dy, uu = u - dy;
        if ((unsigned)yy < (unsigned)HW && (unsigned)uu < (unsigned)JH) {
            float4 g = CA4[((size_t)(yy * HW + x) * JH + uu) * (CP / 4) + q4];
            s.x += g.x; s.y += g.y; s.z += g.z; s.w += g.w;
        }
    }
    if (q4 == 11) { s.z = 0.f; s.w = 0.f; }   // v = 46,47 pad -> zero
    ((float4*)d_Pm)[idx] = s;
}

// ---------------- K7: CB[(y,x)][(u,v)] = sum_dx Pm[y][x+1-dx][u][v-dx], float4 ----------------
// Per dx, EXACTLY ONE shifted element per output lane (diagonal sum, not box sum).
__global__ void cb_kernel() {
    const int n4 = PIX * PIX / 4;             // 1,327,104
    int idx = blockIdx.x * blockDim.x + threadIdx.x;
    if (idx >= n4) return;
    int q4 = idx % 12; int t = idx / 12;
    int u = t % HW;    t /= HW;
    int x = t % HW;    int y = t / HW;
    int v0 = q4 * 4;
    float4 o = make_float4(0.f, 0.f, 0.f, 0.f);
#pragma unroll
    for (int dx = 0; dx < 3; dx++) {
        int xx = x + 1 - dx;
        if ((unsigned)xx < (unsigned)HW) {
            int rowbase = ((y * HW + xx) * HW + u) * CP;
            float4 f = ((const float4*)d_Pm)[rowbase / 4 + q4];
            float sm1 = 0.f, sm2 = 0.f;
            if (v0 > 0) { sm1 = d_Pm[rowbase + v0 - 1]; sm2 = d_Pm[rowbase + v0 - 2]; }
            if (dx == 0) {
                o.x += f.x;  o.y += f.y;  o.z += f.z;  o.w += f.w;
            } else if (dx == 1) {
                o.x += sm1;  o.y += f.x;  o.z += f.y;  o.w += f.z;
            } else {
                o.x += sm2;  o.y += sm1;  o.z += f.x;  o.w += f.y;
            }
        }
    }
    ((float4*)d_CB)[((size_t)(y * HW + x) * 576) + u * 12 + q4] = o;
}

// ---------------- K8: acl partials = CB @ bg, f32x2 packed, B transposed in smem ----------------
__global__ void gemmCB_kernel(int b) {
    __shared__ __align__(16) float Acb[64 * 66];   // [m][k]
    __shared__ __align__(16) float BT[64 * 66];    // [col][k]
    int ks = blockIdx.y;
    int mt = blockIdx.x * 64;
    const float* bgp = d_bg + (size_t)b * PIX * D;
    int tid = threadIdx.x;
    int ty = tid >> 4, tx = tid & 15;
    unsigned long long acc[4][4] = {};
    int kbase = ks * KSEG;
    for (int kt = 0; kt < KSEG; kt += 64) {
        int k0 = kbase + kt;
        for (int i = tid; i < 4096; i += 256) {
            int r = i >> 6, c = i & 63;
            Acb[r * 66 + c] = d_CB[(size_t)(mt + r) * PIX + k0 + c];
            BT[c * 66 + r]  = bgp[(k0 + r) * D + c];
        }
        __syncthreads();
#pragma unroll
        for (int kp = 0; kp < 32; kp++) {
            int k = kp * 2;
            unsigned long long a2[4], b2[4];
#pragma unroll
            for (int i = 0; i < 4; i++) {
                a2[i] = *(const unsigned long long*)&Acb[(ty + 16 * i) * 66 + k];
                b2[i] = *(const unsigned long long*)&BT[(tx + 16 * i) * 66 + k];
            }
#pragma unroll
            for (int i = 0; i < 4; i++)
#pragma unroll
                for (int j = 0; j < 4; j++) ffma2(acc[i][j], a2[i], b2[j]);
        }
        __syncthreads();
    }
    float* outp = d_aclp[ks];
#pragma unroll
    for (int i = 0; i < 4; i++)
#pragma unroll
        for (int j = 0; j < 4; j++)
            outp[(mt + ty + 16 * i) * D + tx + 16 * j] = pairsum(acc[i][j]);
}

// ---------------- K9: ACL + concat + W2 GEMM + ELU ----------------
__global__ void final_kernel(const float* __restrict__ g_in,
                             const float* __restrict__ mask,
                             const float* __restrict__ W2,
                             const float* __restrict__ b2,
                             float* __restrict__ out, int b) {
    __shared__ float w2s[128 * 64];
    __shared__ float cats[4][128];
    int tid = threadIdx.x;
    int g = tid >> 6, dch = tid & 63;
    int pl  = blockIdx.x * 4 + g;
    int pix = b * PIX + pl;
    for (int i = tid; i < 128 * 64; i += 256) w2s[i] = W2[i];

    float gv = g_in[pix * D + dch];
    float m  = mask[pix];
    float a  = 0.f;
#pragma unroll
    for (int s = 0; s < NSPLIT; s++) a += d_aclp[s][pl * D + dch];
    float ACL = d_bg[pix * D + dch] + a * (1.f / 9.f) * (1.f - m);
    cats[g][dch]      = gv;
    cats[g][64 + dch] = ACL;
    __syncthreads();

    float acc = b2[dch];
#pragma unroll 16
    for (int k = 0; k < 128; k++) acc += cats[g][k] * w2s[k * 64 + dch];
    out[pix * D + dch] = acc > 0.f ? acc : expm1f(acc);
}

// ---------------- launch ----------------
extern "C" void kernel_launch(void* const* d_in, const int* in_sizes, int n_in,
                              void* d_out, int out_size) {
    const float* g_in = (const float*)d_in[0];
    const float* mask = (const float*)d_in[1];
    const float* W2   = (const float*)d_in[2];
    const float* b2   = (const float*)d_in[3];
    float* out = (float*)d_out;

    prep_kernel<<<B * PIX / 4, 256>>>(g_in, mask);
    box_kernel<<<(B * PIX + 255) / 256, 256>>>();

    for (int b = 0; b < B; b++) {
        gemmG_kernel<<<dim3(PIX / 64, PIX / 64), 256>>>(g_in, b);
        hbuild_kernel<<<(HW * HW * JH * (HW / 4) + 255) / 256, 256>>>();
        row_kernel<<<PIX, 256>>>(b);
        pm_kernel<<<(HW * HW * HW * (CP / 4) + 255) / 256, 256>>>();
        cb_kernel<<<(PIX * PIX / 4 + 255) / 256, 256>>>();
        gemmCB_kernel<<<dim3(PIX / 64, NSPLIT), 256>>>(b);
        final_kernel<<<PIX / 4, 256>>>(g_in, mask, W2, b2, out, b);
    }
}